// round 10
// baseline (speedup 1.0000x reference)
#include <cuda_runtime.h>
#include <cuda_bf16.h>
#include <cstdint>

// IndRNN on GB300 (compute_103 target -> mma.sync fallback HMMA, no tcgen05):
//   proj = x @ W + b  via bf16 hi/lo 3-term split (x_hi*W_hi + x_lo*W_hi + x_hi*W_lo)
//   h_t  = relu(proj_t + h_{t-1} * clip(u,0,1))  scan in-place on d_out
//
// Inputs: x [64,512,256] f32, h0 [64,512] f32, W [256,512] f32, u [512] f32, b [512] f32.
// Output [64,512,512] f32.

#define BATCH 64
#define TT    512
#define DD    256
#define UU    512
#define MM    (BATCH * TT)      // 32768
#define K2    512               // [hi(256) | lo(256)]

// ---------------- device scratch ----------------
__device__ __align__(16) __nv_bfloat16 g_A2[(size_t)MM * K2];   // 32 MB  [m][hi|lo]
__device__ __align__(16) __nv_bfloat16 g_B2t[(size_t)UU * K2];  // 512 KB [n][hi|lo] (W^T)

// ---------------- PTX helpers (baseline <= sm_80, safe for compute_103) ----------------
__device__ __forceinline__ uint32_t smem_u32(const void* p) {
    uint32_t a;
    asm("{ .reg .u64 t; cvta.to.shared.u64 t, %1; cvt.u32.u64 %0, t; }" : "=r"(a) : "l"(p));
    return a;
}
#define CP16(dst, src) \
    asm volatile("cp.async.cg.shared.global [%0], [%1], 16;" :: "r"(dst), "l"(src) : "memory")
#define CP_COMMIT() asm volatile("cp.async.commit_group;" ::: "memory")
#define CP_WAITN(n) asm volatile("cp.async.wait_group %0;" :: "n"(n) : "memory")

#define LDSM_X4(r0, r1, r2, r3, addr) \
    asm volatile("ldmatrix.sync.aligned.m8n8.x4.shared.b16 {%0,%1,%2,%3}, [%4];" \
        : "=r"(r0), "=r"(r1), "=r"(r2), "=r"(r3) : "r"(addr))

#define MMA_BF16(d, a, b0, b1) \
    asm volatile("mma.sync.aligned.m16n8k16.row.col.f32.bf16.bf16.f32 " \
        "{%0,%1,%2,%3}, {%4,%5,%6,%7}, {%8,%9}, {%0,%1,%2,%3};" \
        : "+f"((d)[0]), "+f"((d)[1]), "+f"((d)[2]), "+f"((d)[3]) \
        : "r"((a)[0]), "r"((a)[1]), "r"((a)[2]), "r"((a)[3]), "r"(b0), "r"(b1))

// ---------------- prep: split x into bf16 hi|lo ----------------
__global__ __launch_bounds__(256) void convert_x(const float4* __restrict__ x4) {
    int idx = blockIdx.x * blockDim.x + threadIdx.x;     // MM*DD/4 = 2097152
    int m  = idx >> 6;
    int k4 = (idx & 63) << 2;
    float4 v = x4[idx];
    __nv_bfloat162 h01 = __floats2bfloat162_rn(v.x, v.y);
    __nv_bfloat162 h23 = __floats2bfloat162_rn(v.z, v.w);
    float lx = v.x - __low2float(h01);
    float ly = v.y - __high2float(h01);
    float lz = v.z - __low2float(h23);
    float lw = v.w - __high2float(h23);
    __nv_bfloat162 l01 = __floats2bfloat162_rn(lx, ly);
    __nv_bfloat162 l23 = __floats2bfloat162_rn(lz, lw);
    __nv_bfloat162* dh = reinterpret_cast<__nv_bfloat162*>(g_A2 + (size_t)m * K2 + k4);
    dh[0] = h01; dh[1] = h23;
    __nv_bfloat162* dl = reinterpret_cast<__nv_bfloat162*>(g_A2 + (size_t)m * K2 + DD + k4);
    dl[0] = l01; dl[1] = l23;
}

// ---------------- prep: split + transpose W ----------------
__global__ __launch_bounds__(256) void convert_w(const float* __restrict__ W) {
    int idx = blockIdx.x * blockDim.x + threadIdx.x;     // 131072
    int n = idx & (UU - 1);
    int k = idx >> 9;
    float w = W[(size_t)k * UU + n];
    __nv_bfloat16 h = __float2bfloat16(w);
    float l = w - __bfloat162float(h);
    g_B2t[(size_t)n * K2 + k]      = h;
    g_B2t[(size_t)n * K2 + DD + k] = __float2bfloat16(l);
}

// ---------------- GEMM via mma.sync ----------------
// CTA 256(M) x 128(N), K-chunk 32, double-buffered cp.async, 8 warps.
// Warp tile 64x64 (mt=4, nt=8) -> 32 independent accumulators innermost; each
// B smem fragment feeds 4 m-tiles (amortizes smem crossbar + halves B L2 traffic).
#define ROWB      80
#define A_ROWS    256
#define ABUF_SZ   (A_ROWS * ROWB)        // 20480 B
#define BBUF_SZ   (128 * ROWB)           // 10240 B
#define OFF_AHI   0
#define OFF_ALO   ABUF_SZ
#define OFF_BHI   (2 * ABUF_SZ)
#define OFF_BLO   (2 * ABUF_SZ + BBUF_SZ)
#define STAGE_SZ  (2 * ABUF_SZ + 2 * BBUF_SZ)   // 61440 B
#define SM_TOTAL  (2 * STAGE_SZ)                // 122880 B

__device__ __forceinline__ void load_chunk(uint32_t stage_base, int bm, int bn, int k0, int tid) {
    const char* gA = reinterpret_cast<const char*>(g_A2);
    const char* gB = reinterpret_cast<const char*>(g_B2t);
#pragma unroll
    for (int r = 0; r < 4; r++) {          // A: 256 rows x 4 segs = 1024 cp per buf
        int idx = tid + r * 256;
        int row = idx >> 2;
        int seg = (idx & 3) << 4;
        uint32_t so = stage_base + row * ROWB + seg;
        const char* srcA = gA + (size_t)(bm + row) * 1024 + k0 * 2 + seg;
        CP16(so + OFF_AHI, srcA);
        CP16(so + OFF_ALO, srcA + 512);
    }
#pragma unroll
    for (int r = 0; r < 2; r++) {          // B: 128 rows x 4 segs = 512 cp per buf
        int idx = tid + r * 256;
        int row = idx >> 2;
        int seg = (idx & 3) << 4;
        uint32_t so = stage_base + row * ROWB + seg;
        const char* srcB = gB + (size_t)(bn + row) * 1024 + k0 * 2 + seg;
        CP16(so + OFF_BHI, srcB);
        CP16(so + OFF_BLO, srcB + 512);
    }
}

__global__ __launch_bounds__(256, 1) void indrnn_gemm_mma(
    const float* __restrict__ bias, float* __restrict__ C)
{
    extern __shared__ char smem[];
    const uint32_t sbase = smem_u32(smem);
    const int tid  = threadIdx.x;
    const int wid  = tid >> 5;
    const int lane = tid & 31;
    const int bm   = blockIdx.y * 256;
    const int bn   = blockIdx.x * 128;
    const int wm   = (wid & 3) * 64;     // warp m offset (4 warps cover 256)
    const int wn   = (wid >> 2) * 64;    // warp n offset (2 warps cover 128)

    float acc[4][8][4];
#pragma unroll
    for (int mt = 0; mt < 4; mt++)
#pragma unroll
        for (int nt = 0; nt < 8; nt++)
#pragma unroll
            for (int i = 0; i < 4; i++) acc[mt][nt][i] = 0.0f;

    load_chunk(sbase,            bm, bn, 0,  tid); CP_COMMIT();
    load_chunk(sbase + STAGE_SZ, bm, bn, 32, tid); CP_COMMIT();

    // per-lane ldmatrix base offsets
    const uint32_t a_base = (wm + (lane & 15)) * ROWB + (lane >> 4) * 16;
    const uint32_t b_base = (wn + ((lane >> 4) & 1) * 8 + (lane & 7)) * ROWB
                          + ((lane >> 3) & 1) * 16;

    for (int c = 0; c < 8; c++) {
        if (c < 7) { CP_WAITN(1); } else { CP_WAITN(0); }
        __syncthreads();

        const uint32_t st  = sbase + (c & 1) * STAGE_SZ;
        const uint32_t aHi = st + OFF_AHI;
        const uint32_t aLo = st + OFF_ALO;
        const uint32_t bHi = st + OFF_BHI;
        const uint32_t bLo = st + OFF_BLO;

#pragma unroll
        for (int k16 = 0; k16 < 2; k16++) {
            const uint32_t kb = k16 * 32;
            uint32_t ah[4][4], al[4][4], bf[8][2];
#pragma unroll
            for (int mt = 0; mt < 4; mt++) {
                LDSM_X4(ah[mt][0], ah[mt][1], ah[mt][2], ah[mt][3],
                        aHi + a_base + mt * (16 * ROWB) + kb);
                LDSM_X4(al[mt][0], al[mt][1], al[mt][2], al[mt][3],
                        aLo + a_base + mt * (16 * ROWB) + kb);
            }
#pragma unroll
            for (int np = 0; np < 4; np++)
                LDSM_X4(bf[2 * np][0], bf[2 * np][1], bf[2 * np + 1][0], bf[2 * np + 1][1],
                        bHi + b_base + np * (16 * ROWB) + kb);

            // term 1: hi*hi  (32 independent accumulators)
#pragma unroll
            for (int nt = 0; nt < 8; nt++)
#pragma unroll
                for (int mt = 0; mt < 4; mt++)
                    MMA_BF16(acc[mt][nt], ah[mt], bf[nt][0], bf[nt][1]);
            // term 2: lo*hi
#pragma unroll
            for (int nt = 0; nt < 8; nt++)
#pragma unroll
                for (int mt = 0; mt < 4; mt++)
                    MMA_BF16(acc[mt][nt], al[mt], bf[nt][0], bf[nt][1]);
            // reload B regs with lo half, term 3: hi*lo
#pragma unroll
            for (int np = 0; np < 4; np++)
                LDSM_X4(bf[2 * np][0], bf[2 * np][1], bf[2 * np + 1][0], bf[2 * np + 1][1],
                        bLo + b_base + np * (16 * ROWB) + kb);
#pragma unroll
            for (int nt = 0; nt < 8; nt++)
#pragma unroll
                for (int mt = 0; mt < 4; mt++)
                    MMA_BF16(acc[mt][nt], ah[mt], bf[nt][0], bf[nt][1]);
        }

        __syncthreads();
        if (c + 2 < 8) { load_chunk(st, bm, bn, (c + 2) * 32, tid); CP_COMMIT(); }
    }

    // epilogue: c-frag thread t holds (m = t/4 [+8], n = (t%4)*2 [+1])
    const int m0   = bm + wm + (lane >> 2);
    const int col0 = bn + wn + (lane & 3) * 2;
#pragma unroll
    for (int mt = 0; mt < 4; mt++) {
#pragma unroll
        for (int nt = 0; nt < 8; nt++) {
            const int r = m0 + mt * 16;
            const int cc = col0 + nt * 8;
            const float2 bv = *reinterpret_cast<const float2*>(bias + cc);
            float2 o0, o1;
            o0.x = acc[mt][nt][0] + bv.x;
            o0.y = acc[mt][nt][1] + bv.y;
            o1.x = acc[mt][nt][2] + bv.x;
            o1.y = acc[mt][nt][3] + bv.y;
            *reinterpret_cast<float2*>(C + (size_t)r * UU + cc)       = o0;
            *reinterpret_cast<float2*>(C + (size_t)(r + 8) * UU + cc) = o1;
        }
    }
}

// ---------------- scan: cp.async smem ring (8 stages x 16 timesteps) ----------------
#define SC_TS    16
#define SC_NS    8
#define SC_STAGE (SC_TS * 128 * 4)          // 8192 B
#define SC_SMEM  (SC_NS * SC_STAGE)         // 65536 B

__device__ __forceinline__ void scan_issue_stage(uint32_t sm_stage, const char* gbase,
                                                 int t0, int tid) {
#pragma unroll
    for (int k = 0; k < 4; k++) {
        int j = tid + k * 128;              // 0..511
        int t = j >> 5;
        int seg = (j & 31) << 4;            // 16B chunks across 512B row
        CP16(sm_stage + t * 512 + seg, gbase + (size_t)(t0 + t) * (UU * 4) + seg);
    }
}

__global__ __launch_bounds__(128) void indrnn_scan(
    const float* __restrict__ h0,
    const float* __restrict__ u,
    float* __restrict__ out)
{
    extern __shared__ float sbuf[];
    const uint32_t sm = smem_u32(sbuf);
    const int tid = threadIdx.x;
    const int u0  = (blockIdx.x & 3) * 128;
    const int bb  = blockIdx.x >> 2;
    const int uu  = u0 + tid;

    const float uc = fminf(fmaxf(u[uu], 0.0f), 1.0f);
    float h = h0[bb * UU + uu];

    float* pout = out + (size_t)bb * TT * UU + uu;
    const char* gbase = reinterpret_cast<const char*>(out)
                      + ((size_t)bb * TT * UU + u0) * 4;

#pragma unroll
    for (int s = 0; s < SC_NS - 1; s++) {
        scan_issue_stage(sm + s * SC_STAGE, gbase, s * SC_TS, tid);
        CP_COMMIT();
    }

#pragma unroll 1
    for (int blk = 0; blk < TT / SC_TS; blk++) {
        CP_WAITN(SC_NS - 2);
        __syncthreads();

        const int nb = blk + SC_NS - 1;
        if (nb < TT / SC_TS) {
            scan_issue_stage(sm + (nb & (SC_NS - 1)) * SC_STAGE, gbase, nb * SC_TS, tid);
        }
        CP_COMMIT();

        const float* stage = sbuf + (blk & (SC_NS - 1)) * (SC_TS * 128) + tid;
        const int t0 = blk * SC_TS;
#pragma unroll
        for (int i = 0; i < SC_TS; i++) {
            h = fmaxf(fmaf(h, uc, stage[i * 128]), 0.0f);
            pout[(size_t)(t0 + i) * UU] = h;
        }
    }
}

extern "C" void kernel_launch(void* const* d_in, const int* in_sizes, int n_in,
                              void* d_out, int out_size)
{
    const float* x  = (const float*)d_in[0];
    const float* h0 = (const float*)d_in[1];
    const float* W  = (const float*)d_in[2];
    const float* u  = (const float*)d_in[3];
    const float* b  = (const float*)d_in[4];
    float* out = (float*)d_out;

    cudaFuncSetAttribute(indrnn_gemm_mma, cudaFuncAttributeMaxDynamicSharedMemorySize, SM_TOTAL);
    cudaFuncSetAttribute(indrnn_scan,     cudaFuncAttributeMaxDynamicSharedMemorySize, SC_SMEM);

    convert_x<<<(MM * DD / 4) / 256, 256>>>(reinterpret_cast<const float4*>(x));
    convert_w<<<(DD * UU) / 256, 256>>>(W);

    dim3 grid(UU / 128, MM / 256);   // (4, 128)
    indrnn_gemm_mma<<<grid, 256, SM_TOTAL>>>(b, out);

    indrnn_scan<<<(BATCH * UU) / 128, 128, SC_SMEM>>>(h0, u, out);
}

// round 11
// speedup vs baseline: 1.3977x; 1.3977x over previous
#include <cuda_runtime.h>
#include <cuda_fp16.h>
#include <cstdint>

// IndRNN on GB300 (compute_103 target -> mma.sync HMMA):
//   proj = x @ W + b  via fp16 2-term split: x = x_hi + x_lo (exact), W = fp16(W)
//          proj ~= x_hi*W + x_lo*W   (only W-rounding error ~2^-12 -> rel ~2e-4)
//   h_t  = relu(proj_t + h_{t-1} * clip(u,0,1))  scan in-place on d_out
//
// Inputs: x [64,512,256] f32, h0 [64,512] f32, W [256,512] f32, u [512] f32, b [512] f32.
// Output [64,512,512] f32.

#define BATCH 64
#define TT    512
#define DD    256
#define UU    512
#define MM    (BATCH * TT)      // 32768
#define K2    512               // A scratch row: [hi(256) | lo(256)] fp16

// ---------------- device scratch ----------------
__device__ __align__(16) __half g_A2[(size_t)MM * K2];   // 32 MB  [m][hi|lo]
__device__ __align__(16) __half g_Bt[(size_t)UU * DD];   // 256 KB [n][k] (W^T, fp16)

// ---------------- PTX helpers (baseline <= sm_80) ----------------
__device__ __forceinline__ uint32_t smem_u32(const void* p) {
    uint32_t a;
    asm("{ .reg .u64 t; cvta.to.shared.u64 t, %1; cvt.u32.u64 %0, t; }" : "=r"(a) : "l"(p));
    return a;
}
#define CP16(dst, src) \
    asm volatile("cp.async.cg.shared.global [%0], [%1], 16;" :: "r"(dst), "l"(src) : "memory")
#define CP_COMMIT() asm volatile("cp.async.commit_group;" ::: "memory")
#define CP_WAITN(n) asm volatile("cp.async.wait_group %0;" :: "n"(n) : "memory")

#define LDSM_X4(r0, r1, r2, r3, addr) \
    asm volatile("ldmatrix.sync.aligned.m8n8.x4.shared.b16 {%0,%1,%2,%3}, [%4];" \
        : "=r"(r0), "=r"(r1), "=r"(r2), "=r"(r3) : "r"(addr))

#define MMA_F16(d, a, b0, b1) \
    asm volatile("mma.sync.aligned.m16n8k16.row.col.f32.f16.f16.f32 " \
        "{%0,%1,%2,%3}, {%4,%5,%6,%7}, {%8,%9}, {%0,%1,%2,%3};" \
        : "+f"((d)[0]), "+f"((d)[1]), "+f"((d)[2]), "+f"((d)[3]) \
        : "r"((a)[0]), "r"((a)[1]), "r"((a)[2]), "r"((a)[3]), "r"(b0), "r"(b1))

// ---------------- prep: split x into fp16 hi|lo (exact 2-word representation) ----------------
__global__ __launch_bounds__(256) void convert_x(const float4* __restrict__ x4) {
    int idx = blockIdx.x * blockDim.x + threadIdx.x;     // MM*DD/4 = 2097152
    int m  = idx >> 6;
    int k4 = (idx & 63) << 2;
    float4 v = x4[idx];
    __half2 h01 = __floats2half2_rn(v.x, v.y);
    __half2 h23 = __floats2half2_rn(v.z, v.w);
    float lx = v.x - __low2float(h01);
    float ly = v.y - __high2float(h01);
    float lz = v.z - __low2float(h23);
    float lw = v.w - __high2float(h23);
    __half2 l01 = __floats2half2_rn(lx, ly);
    __half2 l23 = __floats2half2_rn(lz, lw);
    __half2* dh = reinterpret_cast<__half2*>(g_A2 + (size_t)m * K2 + k4);
    dh[0] = h01; dh[1] = h23;
    __half2* dl = reinterpret_cast<__half2*>(g_A2 + (size_t)m * K2 + DD + k4);
    dl[0] = l01; dl[1] = l23;
}

// ---------------- prep: fp16 + transpose W ----------------
__global__ __launch_bounds__(256) void convert_w(const float* __restrict__ W) {
    int idx = blockIdx.x * blockDim.x + threadIdx.x;     // 131072
    int n = idx & (UU - 1);
    int k = idx >> 9;
    g_Bt[(size_t)n * DD + k] = __float2half_rn(W[(size_t)k * UU + n]);
}

// ---------------- GEMM via mma.sync ----------------
// CTA 128(M) x 128(N), K-chunk 32, 3-stage cp.async ring (single sync per chunk),
// 8 warps, warp tile 32x64 (mt=2, nt=8) -> 16 independent accumulators innermost.
// Both split terms (x_hi, x_lo) share the same B fragments.
#define ROWB      80
#define BUF_SZ    (128 * ROWB)                 // 10240 B
#define OFF_AHI   0
#define OFF_ALO   BUF_SZ
#define OFF_B     (2 * BUF_SZ)
#define STAGE_SZ  (3 * BUF_SZ)                 // 30720 B
#define NSTAGE    3
#define SM_TOTAL  (NSTAGE * STAGE_SZ)          // 92160 B

__device__ __forceinline__ void load_chunk(uint32_t stage_base, int bm, int bn, int k0, int tid) {
    const char* gA = reinterpret_cast<const char*>(g_A2);
    const char* gB = reinterpret_cast<const char*>(g_Bt);
#pragma unroll
    for (int r = 0; r < 2; r++) {
        int idx = tid + r * 256;          // 0..511
        int row = idx >> 2;
        int seg = (idx & 3) << 4;         // 0,16,32,48
        uint32_t so = stage_base + row * ROWB + seg;
        const char* srcA = gA + (size_t)(bm + row) * 1024 + k0 * 2 + seg;  // A row = 1024 B
        const char* srcB = gB + (size_t)(bn + row) * 512  + k0 * 2 + seg;  // B row = 512 B
        CP16(so + OFF_AHI, srcA);         // x_hi
        CP16(so + OFF_ALO, srcA + 512);   // x_lo
        CP16(so + OFF_B,   srcB);         // W
    }
}

__global__ __launch_bounds__(256, 2) void indrnn_gemm_mma(
    const float* __restrict__ bias, float* __restrict__ C)
{
    extern __shared__ char smem[];
    const uint32_t sbase = smem_u32(smem);
    const int tid  = threadIdx.x;
    const int wid  = tid >> 5;
    const int lane = tid & 31;
    const int bm   = blockIdx.y * 128;
    const int bn   = blockIdx.x * 128;
    const int wm   = (wid & 3) * 32;
    const int wn   = (wid >> 2) * 64;

    float acc[2][8][4];
#pragma unroll
    for (int mt = 0; mt < 2; mt++)
#pragma unroll
        for (int nt = 0; nt < 8; nt++)
#pragma unroll
            for (int i = 0; i < 4; i++) acc[mt][nt][i] = 0.0f;

    load_chunk(sbase,            bm, bn, 0,  tid); CP_COMMIT();
    load_chunk(sbase + STAGE_SZ, bm, bn, 32, tid); CP_COMMIT();

    // per-lane ldmatrix base offsets (same geometry as validated R9 kernel)
    const uint32_t a_base = (wm + (lane & 15)) * ROWB + (lane >> 4) * 16;
    const uint32_t b_base = (wn + ((lane >> 4) & 1) * 8 + (lane & 7)) * ROWB
                          + ((lane >> 3) & 1) * 16;

    int stage = 0;   // stage index of chunk c
    for (int c = 0; c < 8; c++) {
        if (c < 7) { CP_WAITN(1); } else { CP_WAITN(0); }
        __syncthreads();   // all warps done with chunk c-1's stage; chunk c data visible

        // issue chunk c+2 into the stage vacated by chunk c-1 (3-stage ring -> no WAR)
        if (c + 2 < 8) {
            int ns = stage + 2; if (ns >= NSTAGE) ns -= NSTAGE;
            load_chunk(sbase + ns * STAGE_SZ, bm, bn, (c + 2) * 32, tid);
            CP_COMMIT();
        }

        const uint32_t st  = sbase + stage * STAGE_SZ;
        const uint32_t aHi = st + OFF_AHI;
        const uint32_t aLo = st + OFF_ALO;
        const uint32_t bSm = st + OFF_B;

#pragma unroll
        for (int k16 = 0; k16 < 2; k16++) {
            const uint32_t kb = k16 * 32;
            uint32_t ah[2][4], al[2][4], bf[8][2];
#pragma unroll
            for (int mt = 0; mt < 2; mt++) {
                LDSM_X4(ah[mt][0], ah[mt][1], ah[mt][2], ah[mt][3],
                        aHi + a_base + mt * (16 * ROWB) + kb);
                LDSM_X4(al[mt][0], al[mt][1], al[mt][2], al[mt][3],
                        aLo + a_base + mt * (16 * ROWB) + kb);
            }
#pragma unroll
            for (int np = 0; np < 4; np++)
                LDSM_X4(bf[2 * np][0], bf[2 * np][1], bf[2 * np + 1][0], bf[2 * np + 1][1],
                        bSm + b_base + np * (16 * ROWB) + kb);

            // term 1: x_hi * W   (16 independent accumulators back-to-back)
#pragma unroll
            for (int nt = 0; nt < 8; nt++) {
                MMA_F16(acc[0][nt], ah[0], bf[nt][0], bf[nt][1]);
                MMA_F16(acc[1][nt], ah[1], bf[nt][0], bf[nt][1]);
            }
            // term 2: x_lo * W   (same B fragments)
#pragma unroll
            for (int nt = 0; nt < 8; nt++) {
                MMA_F16(acc[0][nt], al[0], bf[nt][0], bf[nt][1]);
                MMA_F16(acc[1][nt], al[1], bf[nt][0], bf[nt][1]);
            }
        }

        if (++stage == NSTAGE) stage = 0;
    }

    // epilogue: c-frag thread t holds (m = t/4 [+8], n = (t%4)*2 [+1])
    const int m0   = bm + wm + (lane >> 2);
    const int col0 = bn + wn + (lane & 3) * 2;
#pragma unroll
    for (int mt = 0; mt < 2; mt++) {
#pragma unroll
        for (int nt = 0; nt < 8; nt++) {
            const int r = m0 + mt * 16;
            const int cc = col0 + nt * 8;
            const float2 bv = *reinterpret_cast<const float2*>(bias + cc);
            float2 o0, o1;
            o0.x = acc[mt][nt][0] + bv.x;
            o0.y = acc[mt][nt][1] + bv.y;
            o1.x = acc[mt][nt][2] + bv.x;
            o1.y = acc[mt][nt][3] + bv.y;
            *reinterpret_cast<float2*>(C + (size_t)r * UU + cc)       = o0;
            *reinterpret_cast<float2*>(C + (size_t)(r + 8) * UU + cc) = o1;
        }
    }
}

// ---------------- scan: cp.async smem ring (8 stages x 16 timesteps) ----------------
#define SC_TS    16
#define SC_NS    8
#define SC_STAGE (SC_TS * 128 * 4)          // 8192 B
#define SC_SMEM  (SC_NS * SC_STAGE)         // 65536 B

__device__ __forceinline__ void scan_issue_stage(uint32_t sm_stage, const char* gbase,
                                                 int t0, int tid) {
#pragma unroll
    for (int k = 0; k < 4; k++) {
        int j = tid + k * 128;              // 0..511
        int t = j >> 5;
        int seg = (j & 31) << 4;            // 16B chunks across 512B row
        CP16(sm_stage + t * 512 + seg, gbase + (size_t)(t0 + t) * (UU * 4) + seg);
    }
}

__global__ __launch_bounds__(128) void indrnn_scan(
    const float* __restrict__ h0,
    const float* __restrict__ u,
    float* __restrict__ out)
{
    extern __shared__ float sbuf[];
    const uint32_t sm = smem_u32(sbuf);
    const int tid = threadIdx.x;
    const int u0  = (blockIdx.x & 3) * 128;
    const int bb  = blockIdx.x >> 2;
    const int uu  = u0 + tid;

    const float uc = fminf(fmaxf(u[uu], 0.0f), 1.0f);
    float h = h0[bb * UU + uu];

    float* pout = out + (size_t)bb * TT * UU + uu;
    const char* gbase = reinterpret_cast<const char*>(out)
                      + ((size_t)bb * TT * UU + u0) * 4;

#pragma unroll
    for (int s = 0; s < SC_NS - 1; s++) {
        scan_issue_stage(sm + s * SC_STAGE, gbase, s * SC_TS, tid);
        CP_COMMIT();
    }

#pragma unroll 1
    for (int blk = 0; blk < TT / SC_TS; blk++) {
        CP_WAITN(SC_NS - 2);
        __syncthreads();

        const int nb = blk + SC_NS - 1;
        if (nb < TT / SC_TS) {
            scan_issue_stage(sm + (nb & (SC_NS - 1)) * SC_STAGE, gbase, nb * SC_TS, tid);
        }
        CP_COMMIT();

        const float* stage = sbuf + (blk & (SC_NS - 1)) * (SC_TS * 128) + tid;
        const int t0 = blk * SC_TS;
#pragma unroll
        for (int i = 0; i < SC_TS; i++) {
            h = fmaxf(fmaf(h, uc, stage[i * 128]), 0.0f);
            pout[(size_t)(t0 + i) * UU] = h;
        }
    }
}

extern "C" void kernel_launch(void* const* d_in, const int* in_sizes, int n_in,
                              void* d_out, int out_size)
{
    const float* x  = (const float*)d_in[0];
    const float* h0 = (const float*)d_in[1];
    const float* W  = (const float*)d_in[2];
    const float* u  = (const float*)d_in[3];
    const float* b  = (const float*)d_in[4];
    float* out = (float*)d_out;

    cudaFuncSetAttribute(indrnn_gemm_mma, cudaFuncAttributeMaxDynamicSharedMemorySize, SM_TOTAL);
    cudaFuncSetAttribute(indrnn_scan,     cudaFuncAttributeMaxDynamicSharedMemorySize, SC_SMEM);

    convert_x<<<(MM * DD / 4) / 256, 256>>>(reinterpret_cast<const float4*>(x));
    convert_w<<<(DD * UU) / 256, 256>>>(W);

    dim3 grid(UU / 128, MM / 128);   // (4, 256)
    indrnn_gemm_mma<<<grid, 256, SM_TOTAL>>>(b, out);

    indrnn_scan<<<(BATCH * UU) / 128, 128, SC_SMEM>>>(h0, u, out);
}

// round 13
// speedup vs baseline: 2.0106x; 1.4385x over previous
#include <cuda_runtime.h>
#include <cuda_fp16.h>
#include <cstdint>

// IndRNN on GB300 (compute_103 target -> mma.sync HMMA):
//   proj = fp16(x) @ fp16(W) + b   (single-term; rel_err ~3e-4 << 1e-3 gate)
//   h_t  = relu(proj_t + h_{t-1} * clip(u,0,1))  scan in-place on d_out
//
// x is loaded as fp32 straight into smem; A-fragments are built in registers
// (LDS.64 + cvt) -> no separate x-conversion kernel, no fp16-x scratch.
//
// Inputs: x [64,512,256] f32, h0 [64,512] f32, W [256,512] f32, u [512] f32, b [512] f32.
// Output [64,512,512] f32.

#define BATCH 64
#define TT    512
#define DD    256
#define UU    512
#define MM    (BATCH * TT)      // 32768

// ---------------- device scratch ----------------
__device__ __align__(16) __half g_Bt[(size_t)UU * DD];   // 256 KB [n][k] (W^T, fp16)

// ---------------- PTX helpers (baseline <= sm_80) ----------------
__device__ __forceinline__ uint32_t smem_u32(const void* p) {
    uint32_t a;
    asm("{ .reg .u64 t; cvta.to.shared.u64 t, %1; cvt.u32.u64 %0, t; }" : "=r"(a) : "l"(p));
    return a;
}
#define CP16(dst, src) \
    asm volatile("cp.async.cg.shared.global [%0], [%1], 16;" :: "r"(dst), "l"(src) : "memory")
#define CP_COMMIT() asm volatile("cp.async.commit_group;" ::: "memory")
#define CP_WAITN(n) asm volatile("cp.async.wait_group %0;" :: "n"(n) : "memory")

#define LDSM_X4(r0, r1, r2, r3, addr) \
    asm volatile("ldmatrix.sync.aligned.m8n8.x4.shared.b16 {%0,%1,%2,%3}, [%4];" \
        : "=r"(r0), "=r"(r1), "=r"(r2), "=r"(r3) : "r"(addr))

#define LDS64F(x, y, addr) \
    asm volatile("ld.shared.v2.f32 {%0,%1}, [%2];" : "=f"(x), "=f"(y) : "r"(addr))

#define MMA_F16(d, a, b0, b1) \
    asm volatile("mma.sync.aligned.m16n8k16.row.col.f32.f16.f16.f32 " \
        "{%0,%1,%2,%3}, {%4,%5,%6,%7}, {%8,%9}, {%0,%1,%2,%3};" \
        : "+f"((d)[0]), "+f"((d)[1]), "+f"((d)[2]), "+f"((d)[3]) \
        : "r"((a)[0]), "r"((a)[1]), "r"((a)[2]), "r"((a)[3]), "r"(b0), "r"(b1))

__device__ __forceinline__ uint32_t f2h2(float lo, float hi) {
    __half2 h = __floats2half2_rn(lo, hi);     // lo -> bits[0:15], hi -> bits[16:31]
    return *reinterpret_cast<uint32_t*>(&h);
}

// ---------------- prep: fp16 + transpose W ----------------
__global__ __launch_bounds__(256) void convert_w(const float* __restrict__ W) {
    int idx = blockIdx.x * blockDim.x + threadIdx.x;     // 131072
    int n = idx & (UU - 1);
    int k = idx >> 9;
    g_Bt[(size_t)n * DD + k] = __float2half_rn(W[(size_t)k * UU + n]);
}

// ---------------- GEMM via mma.sync ----------------
// CTA 128(M) x 128(N), K-chunk 32, 3-stage cp.async ring, 8 warps,
// warp tile 32x64 (mt=2, nt=8) -> 16 independent accumulators innermost.
// A kept fp32 in smem (row stride 160B: conflict-free LDS.64); frags via cvt.
#define ROWA      160                          // bytes per A smem row (32 floats + pad)
#define ABUF      (128 * ROWA)                 // 20480 B
#define ROWB      80
#define BBUF      (128 * ROWB)                 // 10240 B
#define OFF_B     ABUF
#define STAGE_SZ  (ABUF + BBUF)                // 30720 B
#define NSTAGE    3
#define SM_TOTAL  (NSTAGE * STAGE_SZ)          // 92160 B

__device__ __forceinline__ void load_chunk(uint32_t stage_base, const char* gx,
                                           int bm, int bn, int k0, int tid) {
    const char* gB = reinterpret_cast<const char*>(g_Bt);
    // A: fp32, 128 rows x 128 B  -> 1024 cp16 (4 per thread)
#pragma unroll
    for (int r = 0; r < 4; r++) {
        int idx = tid + r * 256;
        int row = idx >> 3;
        int seg = (idx & 7) << 4;
        CP16(stage_base + row * ROWA + seg,
             gx + (size_t)(bm + row) * 1024 + k0 * 4 + seg);
    }
    // B: fp16, 128 rows x 64 B -> 512 cp16 (2 per thread)
#pragma unroll
    for (int r = 0; r < 2; r++) {
        int idx = tid + r * 256;
        int row = idx >> 2;
        int seg = (idx & 3) << 4;
        CP16(stage_base + OFF_B + row * ROWB + seg,
             gB + (size_t)(bn + row) * 512 + k0 * 2 + seg);
    }
}

__global__ __launch_bounds__(256, 2) void indrnn_gemm_mma(
    const float* __restrict__ X, const float* __restrict__ bias, float* __restrict__ C)
{
    extern __shared__ char smem[];
    const uint32_t sbase = smem_u32(smem);
    const char* gx = reinterpret_cast<const char*>(X);
    const int tid  = threadIdx.x;
    const int wid  = tid >> 5;
    const int lane = tid & 31;
    const int bm   = blockIdx.y * 128;
    const int bn   = blockIdx.x * 128;
    const int wm   = (wid & 3) * 32;
    const int wn   = (wid >> 2) * 64;

    float acc[2][8][4];
#pragma unroll
    for (int mt = 0; mt < 2; mt++)
#pragma unroll
        for (int nt = 0; nt < 8; nt++)
#pragma unroll
            for (int i = 0; i < 4; i++) acc[mt][nt][i] = 0.0f;

    load_chunk(sbase,            gx, bm, bn, 0,  tid); CP_COMMIT();
    load_chunk(sbase + STAGE_SZ, gx, bm, bn, 32, tid); CP_COMMIT();

    // A-frag addressing (fp32 smem): row = wm + mt*16 + g (+8), col = 2t (+1, +8)
    const int g = lane >> 2;
    const int t = lane & 3;
    const uint32_t a_base = (wm + g) * ROWA + t * 8;     // byte offset of (row g, col 2t)
    // B ldmatrix base (validated geometry)
    const uint32_t b_base = (wn + ((lane >> 4) & 1) * 8 + (lane & 7)) * ROWB
                          + ((lane >> 3) & 1) * 16;

    int stage = 0;
    for (int c = 0; c < 8; c++) {
        if (c < 7) { CP_WAITN(1); } else { CP_WAITN(0); }
        __syncthreads();   // chunk c visible; all warps vacated stage of chunk c-1

        if (c + 2 < 8) {
            int ns = stage + 2; if (ns >= NSTAGE) ns -= NSTAGE;
            load_chunk(sbase + ns * STAGE_SZ, gx, bm, bn, (c + 2) * 32, tid);
            CP_COMMIT();
        }

        const uint32_t aSm = sbase + stage * STAGE_SZ;
        const uint32_t bSm = aSm + OFF_B;

#pragma unroll
        for (int k16 = 0; k16 < 2; k16++) {
            const uint32_t kbA = k16 * 64;    // 16 cols * 4 B
            const uint32_t kbB = k16 * 32;    // 16 cols * 2 B

            // A fragments: LDS.64 fp32 pairs -> cvt to f16x2
            uint32_t af[2][4];
#pragma unroll
            for (int mt = 0; mt < 2; mt++) {
                const uint32_t ab = aSm + a_base + mt * (16 * ROWA) + kbA;
                float x0, y0, x1, y1, x2, y2, x3, y3;
                LDS64F(x0, y0, ab);                    // row g,   k 2t..2t+1
                LDS64F(x1, y1, ab + 8 * ROWA);         // row g+8, k 2t..2t+1
                LDS64F(x2, y2, ab + 32);               // row g,   k 2t+8..9
                LDS64F(x3, y3, ab + 8 * ROWA + 32);    // row g+8, k 2t+8..9
                af[mt][0] = f2h2(x0, y0);
                af[mt][1] = f2h2(x1, y1);
                af[mt][2] = f2h2(x2, y2);
                af[mt][3] = f2h2(x3, y3);
            }

            uint32_t bf[8][2];
#pragma unroll
            for (int np = 0; np < 4; np++)
                LDSM_X4(bf[2 * np][0], bf[2 * np][1], bf[2 * np + 1][0], bf[2 * np + 1][1],
                        bSm + b_base + np * (16 * ROWB) + kbB);

            // 16 independent accumulators back-to-back
#pragma unroll
            for (int nt = 0; nt < 8; nt++) {
                MMA_F16(acc[0][nt], af[0], bf[nt][0], bf[nt][1]);
                MMA_F16(acc[1][nt], af[1], bf[nt][0], bf[nt][1]);
            }
        }

        if (++stage == NSTAGE) stage = 0;
    }

    // epilogue: c-frag thread t holds (m = lane/4 [+8], n = (lane%4)*2 [+1])
    const int m0   = bm + wm + (lane >> 2);
    const int col0 = bn + wn + (lane & 3) * 2;
#pragma unroll
    for (int mt = 0; mt < 2; mt++) {
#pragma unroll
        for (int nt = 0; nt < 8; nt++) {
            const int r = m0 + mt * 16;
            const int cc = col0 + nt * 8;
            const float2 bv = *reinterpret_cast<const float2*>(bias + cc);
            float2 o0, o1;
            o0.x = acc[mt][nt][0] + bv.x;
            o0.y = acc[mt][nt][1] + bv.y;
            o1.x = acc[mt][nt][2] + bv.x;
            o1.y = acc[mt][nt][3] + bv.y;
            *reinterpret_cast<float2*>(C + (size_t)r * UU + cc)       = o0;
            *reinterpret_cast<float2*>(C + (size_t)(r + 8) * UU + cc) = o1;
        }
    }
}

// ---------------- scan: cp.async smem ring (8 stages x 16 timesteps) ----------------
#define SC_TS    16
#define SC_NS    8
#define SC_STAGE (SC_TS * 128 * 4)          // 8192 B
#define SC_SMEM  (SC_NS * SC_STAGE)         // 65536 B

__device__ __forceinline__ void scan_issue_stage(uint32_t sm_stage, const char* gbase,
                                                 int t0, int tid) {
#pragma unroll
    for (int k = 0; k < 4; k++) {
        int j = tid + k * 128;              // 0..511
        int t = j >> 5;
        int seg = (j & 31) << 4;            // 16B chunks across 512B row
        CP16(sm_stage + t * 512 + seg, gbase + (size_t)(t0 + t) * (UU * 4) + seg);
    }
}

__global__ __launch_bounds__(128) void indrnn_scan(
    const float* __restrict__ h0,
    const float* __restrict__ u,
    float* __restrict__ out)
{
    extern __shared__ float sbuf[];
    const uint32_t sm = smem_u32(sbuf);
    const int tid = threadIdx.x;
    const int u0  = (blockIdx.x & 3) * 128;
    const int bb  = blockIdx.x >> 2;
    const int uu  = u0 + tid;

    const float uc = fminf(fmaxf(u[uu], 0.0f), 1.0f);
    float h = h0[bb * UU + uu];

    float* pout = out + (size_t)bb * TT * UU + uu;
    const char* gbase = reinterpret_cast<const char*>(out)
                      + ((size_t)bb * TT * UU + u0) * 4;

#pragma unroll
    for (int s = 0; s < SC_NS - 1; s++) {
        scan_issue_stage(sm + s * SC_STAGE, gbase, s * SC_TS, tid);
        CP_COMMIT();
    }

#pragma unroll 1
    for (int blk = 0; blk < TT / SC_TS; blk++) {
        CP_WAITN(SC_NS - 2);
        __syncthreads();

        const int nb = blk + SC_NS - 1;
        if (nb < TT / SC_TS) {
            scan_issue_stage(sm + (nb & (SC_NS - 1)) * SC_STAGE, gbase, nb * SC_TS, tid);
        }
        CP_COMMIT();

        const float* stage = sbuf + (blk & (SC_NS - 1)) * (SC_TS * 128) + tid;
        const int t0 = blk * SC_TS;
#pragma unroll
        for (int i = 0; i < SC_TS; i++) {
            h = fmaxf(fmaf(h, uc, stage[i * 128]), 0.0f);
            pout[(size_t)(t0 + i) * UU] = h;
        }
    }
}

extern "C" void kernel_launch(void* const* d_in, const int* in_sizes, int n_in,
                              void* d_out, int out_size)
{
    const float* x  = (const float*)d_in[0];
    const float* h0 = (const float*)d_in[1];
    const float* W  = (const float*)d_in[2];
    const float* u  = (const float*)d_in[3];
    const float* b  = (const float*)d_in[4];
    float* out = (float*)d_out;

    cudaFuncSetAttribute(indrnn_gemm_mma, cudaFuncAttributeMaxDynamicSharedMemorySize, SM_TOTAL);
    cudaFuncSetAttribute(indrnn_scan,     cudaFuncAttributeMaxDynamicSharedMemorySize, SC_SMEM);

    convert_w<<<(DD * UU) / 256, 256>>>(W);

    dim3 grid(UU / 128, MM / 128);   // (4, 256)
    indrnn_gemm_mma<<<grid, 256, SM_TOTAL>>>(x, b, out);

    indrnn_scan<<<(BATCH * UU) / 128, 128, SC_SMEM>>>(h0, u, out);
}